// round 3
// baseline (speedup 1.0000x reference)
#include <cuda_runtime.h>

#define MAX_NODES 100000
#define MAX_EDGES 1600000
#define D 128
#define SCAN_T 1024

// ---------------------------------------------------------------------------
// Device scratch (static allocation — no cudaMalloc allowed)
// ---------------------------------------------------------------------------
__device__ float g_comb[(size_t)MAX_NODES * D];   // combined = feat + neighbor
__device__ int   g_cnt[MAX_NODES];                // degree histogram
__device__ int   g_start[MAX_NODES + 1];          // CSR row offsets
__device__ int   g_cursor[MAX_NODES];             // fill cursors
__device__ int   g_cols[MAX_EDGES];               // CSR col indices
__device__ float g_vals[MAX_EDGES];               // CSR values

// f32x2 packed-math helpers (SASS FFMA2 — 2 fp32 FMAs per instruction)
#define PACK2(d, lo, hi) \
    asm("mov.b64 %0, {%1, %2};" : "=l"(d) : "f"(lo), "f"(hi))
#define UNPACK2(lo, hi, s) \
    asm("mov.b64 {%0, %1}, %2;" : "=f"(lo), "=f"(hi) : "l"(s))
#define FMA2(d, a, b, c) \
    asm("fma.rn.f32x2 %0, %1, %2, %3;" : "=l"(d) : "l"(a), "l"(b), "l"(c))

// ---------------------------------------------------------------------------
// CSR build: zero counts -> histogram -> scan -> bucket fill
// ---------------------------------------------------------------------------
__global__ void zero_cnt(int n_nodes) {
    int i = blockIdx.x * blockDim.x + threadIdx.x;
    if (i < n_nodes) g_cnt[i] = 0;
}

__global__ void hist_kernel(const int* __restrict__ row_idx, int n_edges) {
    int e = blockIdx.x * blockDim.x + threadIdx.x;
    if (e < n_edges) atomicAdd(&g_cnt[__ldg(row_idx + e)], 1);
}

// Single-block exclusive scan of g_cnt (100K elems, ~98 per thread).
__global__ void __launch_bounds__(SCAN_T) scan_kernel(int n_nodes) {
    __shared__ int sm[SCAN_T];
    int tid = threadIdx.x;
    int chunk = (n_nodes + SCAN_T - 1) / SCAN_T;
    int lo = tid * chunk;
    int hi = min(lo + chunk, n_nodes);

    int s = 0;
    for (int j = lo; j < hi; j++) s += g_cnt[j];
    sm[tid] = s;
    __syncthreads();

    // Hillis-Steele inclusive scan
    for (int off = 1; off < SCAN_T; off <<= 1) {
        int v = (tid >= off) ? sm[tid - off] : 0;
        __syncthreads();
        sm[tid] += v;
        __syncthreads();
    }

    int pref = (tid > 0) ? sm[tid - 1] : 0;   // exclusive prefix
    for (int j = lo; j < hi; j++) {
        g_start[j]  = pref;
        g_cursor[j] = pref;
        pref += g_cnt[j];
    }
    if (tid == SCAN_T - 1) g_start[n_nodes] = pref;
}

__global__ void fill_kernel(const int* __restrict__ row_idx,
                            const int* __restrict__ col_idx,
                            const float* __restrict__ val, int n_edges) {
    int e = blockIdx.x * blockDim.x + threadIdx.x;
    if (e < n_edges) {
        int r = __ldg(row_idx + e);
        int p = atomicAdd(&g_cursor[r], 1);
        g_cols[p] = __ldg(col_idx + e);
        g_vals[p] = __ldg(val + e);
    }
}

// ---------------------------------------------------------------------------
// Gather: one warp per node. combined[n] = feat[n] + sum_j v_j * feat[c_j]
// Lane handles 4 of the 128 features (float4). No atomics, single write.
// ---------------------------------------------------------------------------
__global__ void __launch_bounds__(256) gather_kernel(
    const float* __restrict__ feat, int n_nodes)
{
    int node = blockIdx.x * 8 + (threadIdx.x >> 5);
    int lane = threadIdx.x & 31;
    if (node >= n_nodes) return;

    int s = g_start[node];
    int e = g_start[node + 1];

    // residual (1+eps)*feat with eps = 0
    float4 acc = *reinterpret_cast<const float4*>(
        feat + (size_t)node * D + lane * 4);

    int j = s;
    for (; j + 1 < e; j += 2) {
        int   c0 = __ldg(g_cols + j);
        float v0 = __ldg(g_vals + j);
        int   c1 = __ldg(g_cols + j + 1);
        float v1 = __ldg(g_vals + j + 1);
        float4 f0 = *reinterpret_cast<const float4*>(
            feat + (size_t)c0 * D + lane * 4);
        float4 f1 = *reinterpret_cast<const float4*>(
            feat + (size_t)c1 * D + lane * 4);
        acc.x = fmaf(v0, f0.x, acc.x); acc.y = fmaf(v0, f0.y, acc.y);
        acc.z = fmaf(v0, f0.z, acc.z); acc.w = fmaf(v0, f0.w, acc.w);
        acc.x = fmaf(v1, f1.x, acc.x); acc.y = fmaf(v1, f1.y, acc.y);
        acc.z = fmaf(v1, f1.z, acc.z); acc.w = fmaf(v1, f1.w, acc.w);
    }
    if (j < e) {
        int   c0 = __ldg(g_cols + j);
        float v0 = __ldg(g_vals + j);
        float4 f0 = *reinterpret_cast<const float4*>(
            feat + (size_t)c0 * D + lane * 4);
        acc.x = fmaf(v0, f0.x, acc.x); acc.y = fmaf(v0, f0.y, acc.y);
        acc.z = fmaf(v0, f0.z, acc.z); acc.w = fmaf(v0, f0.w, acc.w);
    }

    *reinterpret_cast<float4*>(g_comb + (size_t)node * D + lane * 4) = acc;
}

// ---------------------------------------------------------------------------
// Fused MLP with packed f32x2 FMAs, paired over K:
//   acc2 lo-half accumulates even-k, hi-half odd-k; halves summed at end.
// Block tile 64 nodes x 128 cols; thread = 8 nodes x 4 cols.
// ---------------------------------------------------------------------------
__global__ void __launch_bounds__(256) fused_mlp(
    const float* __restrict__ W1, const float* __restrict__ b1,
    const float* __restrict__ W2, const float* __restrict__ b2,
    float* __restrict__ out, int n_nodes)
{
    __shared__ float xs[64][D];   // 32 KB, reused for X then H

    const int tid   = threadIdx.x;
    const int cg    = tid & 31;   // col group: cols 4cg .. 4cg+3
    const int ng    = tid >> 5;   // node group: rows 8ng .. 8ng+7
    const int node0 = blockIdx.x * 64;

    // --- load X tile ---
    #pragma unroll
    for (int i = 0; i < 8; i++) {
        int idx  = tid + i * 256;
        int nrow = idx >> 5;
        int c4   = idx & 31;
        int gn   = node0 + nrow;
        float4 vv = (gn < n_nodes)
            ? reinterpret_cast<const float4*>(g_comb + (size_t)gn * D)[c4]
            : make_float4(0.f, 0.f, 0.f, 0.f);
        reinterpret_cast<float4*>(&xs[nrow][0])[c4] = vv;
    }
    __syncthreads();

    unsigned long long acc[8][4];

    // ===== GEMM1: H = relu(X @ W1 + b1) =====
    {
        float4 bb = __ldg(reinterpret_cast<const float4*>(b1) + cg);
        #pragma unroll
        for (int i = 0; i < 8; i++) {
            PACK2(acc[i][0], bb.x, 0.f); PACK2(acc[i][1], bb.y, 0.f);
            PACK2(acc[i][2], bb.z, 0.f); PACK2(acc[i][3], bb.w, 0.f);
        }
    }
    #pragma unroll 4
    for (int k = 0; k < D; k += 2) {
        float4 wA = __ldg(reinterpret_cast<const float4*>(W1 + k * D) + cg);
        float4 wB = __ldg(reinterpret_cast<const float4*>(W1 + (k + 1) * D) + cg);
        unsigned long long w0, w1, w2, w3;
        PACK2(w0, wA.x, wB.x); PACK2(w1, wA.y, wB.y);
        PACK2(w2, wA.z, wB.z); PACK2(w3, wA.w, wB.w);
        #pragma unroll
        for (int i = 0; i < 8; i++) {
            unsigned long long xx =
                *reinterpret_cast<const unsigned long long*>(&xs[ng * 8 + i][k]);
            FMA2(acc[i][0], xx, w0, acc[i][0]);
            FMA2(acc[i][1], xx, w1, acc[i][1]);
            FMA2(acc[i][2], xx, w2, acc[i][2]);
            FMA2(acc[i][3], xx, w3, acc[i][3]);
        }
    }
    __syncthreads();   // all X reads complete before overwrite

    // --- relu(lo+hi) -> H tile ---
    #pragma unroll
    for (int i = 0; i < 8; i++) {
        float lo, hi;
        float4 h4;
        UNPACK2(lo, hi, acc[i][0]); h4.x = fmaxf(lo + hi, 0.f);
        UNPACK2(lo, hi, acc[i][1]); h4.y = fmaxf(lo + hi, 0.f);
        UNPACK2(lo, hi, acc[i][2]); h4.z = fmaxf(lo + hi, 0.f);
        UNPACK2(lo, hi, acc[i][3]); h4.w = fmaxf(lo + hi, 0.f);
        reinterpret_cast<float4*>(&xs[ng * 8 + i][0])[cg] = h4;
    }
    __syncthreads();

    // ===== GEMM2: OUT = H @ W2 + b2 =====
    {
        float4 bb = __ldg(reinterpret_cast<const float4*>(b2) + cg);
        #pragma unroll
        for (int i = 0; i < 8; i++) {
            PACK2(acc[i][0], bb.x, 0.f); PACK2(acc[i][1], bb.y, 0.f);
            PACK2(acc[i][2], bb.z, 0.f); PACK2(acc[i][3], bb.w, 0.f);
        }
    }
    #pragma unroll 4
    for (int k = 0; k < D; k += 2) {
        float4 wA = __ldg(reinterpret_cast<const float4*>(W2 + k * D) + cg);
        float4 wB = __ldg(reinterpret_cast<const float4*>(W2 + (k + 1) * D) + cg);
        unsigned long long w0, w1, w2, w3;
        PACK2(w0, wA.x, wB.x); PACK2(w1, wA.y, wB.y);
        PACK2(w2, wA.z, wB.z); PACK2(w3, wA.w, wB.w);
        #pragma unroll
        for (int i = 0; i < 8; i++) {
            unsigned long long xx =
                *reinterpret_cast<const unsigned long long*>(&xs[ng * 8 + i][k]);
            FMA2(acc[i][0], xx, w0, acc[i][0]);
            FMA2(acc[i][1], xx, w1, acc[i][1]);
            FMA2(acc[i][2], xx, w2, acc[i][2]);
            FMA2(acc[i][3], xx, w3, acc[i][3]);
        }
    }

    // --- store lo+hi ---
    #pragma unroll
    for (int i = 0; i < 8; i++) {
        int gn = node0 + ng * 8 + i;
        if (gn < n_nodes) {
            float lo, hi;
            float4 o4;
            UNPACK2(lo, hi, acc[i][0]); o4.x = lo + hi;
            UNPACK2(lo, hi, acc[i][1]); o4.y = lo + hi;
            UNPACK2(lo, hi, acc[i][2]); o4.z = lo + hi;
            UNPACK2(lo, hi, acc[i][3]); o4.w = lo + hi;
            reinterpret_cast<float4*>(out + (size_t)gn * D)[cg] = o4;
        }
    }
}

// ---------------------------------------------------------------------------
// Launch. Inputs: indices(2,E) i32, values(E) f32, features(N,128) f32,
// W1(128,128), b1(128), W2(128,128), b2(128). Output f32 (N,128).
// ---------------------------------------------------------------------------
extern "C" void kernel_launch(void* const* d_in, const int* in_sizes, int n_in,
                              void* d_out, int out_size)
{
    const int*   indices  = (const int*)d_in[0];
    const float* values   = (const float*)d_in[1];
    const float* features = (const float*)d_in[2];
    const float* W1       = (const float*)d_in[3];
    const float* b1       = (const float*)d_in[4];
    const float* W2       = (const float*)d_in[5];
    const float* b2       = (const float*)d_in[6];
    float*       out      = (float*)d_out;

    const int n_edges = in_sizes[1];
    const int n_nodes = in_sizes[2] / D;

    const int* row_idx = indices;
    const int* col_idx = indices + n_edges;

    // CSR build
    zero_cnt<<<(n_nodes + 255) / 256, 256>>>(n_nodes);
    hist_kernel<<<(n_edges + 255) / 256, 256>>>(row_idx, n_edges);
    scan_kernel<<<1, SCAN_T>>>(n_nodes);
    fill_kernel<<<(n_edges + 255) / 256, 256>>>(row_idx, col_idx, values,
                                                n_edges);

    // combined = feat + A*feat   (warp per node, no atomics)
    gather_kernel<<<(n_nodes + 7) / 8, 256>>>(features, n_nodes);

    // out = relu(combined @ W1 + b1) @ W2 + b2  (packed f32x2 FMAs)
    fused_mlp<<<(n_nodes + 63) / 64, 256>>>(W1, b1, W2, b2, out, n_nodes);
}

// round 5
// speedup vs baseline: 1.1051x; 1.1051x over previous
#include <cuda_runtime.h>
#include <cuda_bf16.h>

#define MAX_NODES 100000
#define D 128
#define TILE_M 128

// ---------------------------------------------------------------------------
// Device scratch
// ---------------------------------------------------------------------------
__device__ float g_comb[(size_t)MAX_NODES * D];
// B-fragment images for mma.sync m16n8k16 (bf16): W1hi, W1lo, W2hi, W2lo.
// Each image: [s(8 k-steps)][t(16 n-tiles)][lane(32)] -> uint2 {b0,b1}.
__device__ __align__(16) uint2 g_wfrag[4 * 4096];

// ---------------------------------------------------------------------------
// Kernel 1: combined = features  (proven R2)
// ---------------------------------------------------------------------------
__global__ void init_combined(const float* __restrict__ feat, int n_vec4) {
    int i = blockIdx.x * blockDim.x + threadIdx.x;
    if (i < n_vec4)
        reinterpret_cast<float4*>(g_comb)[i] =
            reinterpret_cast<const float4*>(feat)[i];
}

// ---------------------------------------------------------------------------
// Kernel 2: edge scatter, warp per edge, red.global.add.v4.f32  (proven R2)
// ---------------------------------------------------------------------------
__global__ void __launch_bounds__(256) edge_scatter(
    const int* __restrict__ row_idx, const int* __restrict__ col_idx,
    const float* __restrict__ val, const float* __restrict__ feat, int n_edges)
{
    int e = blockIdx.x * 8 + (threadIdx.x >> 5);
    int lane = threadIdx.x & 31;
    if (e >= n_edges) return;

    int r = __ldg(row_idx + e);
    int c = __ldg(col_idx + e);
    float v = __ldg(val + e);

    const float4 f = *reinterpret_cast<const float4*>(feat + (size_t)c * D + lane * 4);
    float mx = f.x * v, my = f.y * v, mz = f.z * v, mw = f.w * v;

    float* dst = g_comb + (size_t)r * D + lane * 4;
    asm volatile("red.global.add.v4.f32 [%0], {%1, %2, %3, %4};"
                 :: "l"(dst), "f"(mx), "f"(my), "f"(mz), "f"(mw) : "memory");
}

// ---------------------------------------------------------------------------
// bf16 split helpers
// ---------------------------------------------------------------------------
__device__ __forceinline__ void split1(float a, unsigned short& h, unsigned short& l) {
    __nv_bfloat16 hb = __float2bfloat16(a);
    __nv_bfloat16 lb = __float2bfloat16(a - __bfloat162float(hb));
    h = __bfloat16_as_ushort(hb);
    l = __bfloat16_as_ushort(lb);
}
__device__ __forceinline__ void split2(float a, float b, unsigned& hp, unsigned& lp) {
    unsigned short ha, la, hb, lb;
    split1(a, ha, la);
    split1(b, hb, lb);
    hp = (unsigned)ha | ((unsigned)hb << 16);
    lp = (unsigned)la | ((unsigned)lb << 16);
}

// ---------------------------------------------------------------------------
// Kernel 3: weight prep -> B fragments (hi/lo), fragment-register order.
// B = W (K x N, row-major W[k][n]). m16n8k16 col-B fragment for lane T:
//   b0 = {B[k0][n], B[k0+1][n]},  b1 = {B[k0+8][n], B[k0+9][n]}
//   k0 = s*16 + (T%4)*2,  n = t*8 + T/4
// 8192 threads: (which W) x (s,t,lane); each writes hi and lo uint2.
// ---------------------------------------------------------------------------
__global__ void wprep(const float* __restrict__ W1, const float* __restrict__ W2) {
    int idx = blockIdx.x * 256 + threadIdx.x;         // 0..8191
    if (idx >= 8192) return;
    int which = idx >> 12;                            // 0:W1 1:W2
    int f = idx & 4095;                               // (s*16+t)*32 + T
    int T = f & 31;
    int st = f >> 5;
    int s = st >> 4, t = st & 15;
    int n  = t * 8 + (T >> 2);
    int k0 = s * 16 + (T & 3) * 2;

    const float* W = which ? W2 : W1;
    float v00 = __ldg(W + k0 * D + n);
    float v01 = __ldg(W + (k0 + 1) * D + n);
    float v10 = __ldg(W + (k0 + 8) * D + n);
    float v11 = __ldg(W + (k0 + 9) * D + n);

    unsigned h0, l0, h1, l1;
    split2(v00, v01, h0, l0);
    split2(v10, v11, h1, l1);

    uint2* hi = g_wfrag + which * 8192;               // W1hi at 0, W2hi at 8192
    uint2* lo = hi + 4096;                            // lo image follows hi
    hi[f] = make_uint2(h0, h1);
    lo[f] = make_uint2(l0, l1);
}

// ---------------------------------------------------------------------------
// Kernel 4: fused MLP via mma.sync bf16 (3-pass split per GEMM).
// Block: 256 threads / 8 warps, tile = 128 nodes x 128 cols.
// Warp w owns rows [w*16, w*16+16). acc: 16 n-tiles x 4 f32.
// ---------------------------------------------------------------------------
#define A_STRIDE 288                      // bytes per row (128 bf16 + 16 pad)
#define AH_OFF   0
#define AL_OFF   36864
#define B1_OFF   73728
#define B2_OFF   74240
#define SMEM_TOT 74752

__device__ __forceinline__ void mma_bf16(float& c0, float& c1, float& c2, float& c3,
                                         unsigned a0, unsigned a1, unsigned a2,
                                         unsigned a3, unsigned b0, unsigned b1) {
    asm volatile(
        "mma.sync.aligned.m16n8k16.row.col.f32.bf16.bf16.f32 "
        "{%0,%1,%2,%3}, {%4,%5,%6,%7}, {%8,%9}, {%0,%1,%2,%3};"
        : "+f"(c0), "+f"(c1), "+f"(c2), "+f"(c3)
        : "r"(a0), "r"(a1), "r"(a2), "r"(a3), "r"(b0), "r"(b1));
}

// One pass: acc += A_img (smem) x W_frag (global, L1-hot)
__device__ __forceinline__ void gemm_pass(const unsigned char* smem, int a_off,
                                          const uint2* __restrict__ wfrag,
                                          float acc[16][4], int r0, int lane) {
    const int c0 = (lane & 3) * 2;
    #pragma unroll
    for (int s = 0; s < 8; s++) {
        const unsigned char* base = smem + a_off + (s * 16 + c0) * 2;
        unsigned a0 = *reinterpret_cast<const unsigned*>(base + r0 * A_STRIDE);
        unsigned a1 = *reinterpret_cast<const unsigned*>(base + (r0 + 8) * A_STRIDE);
        unsigned a2 = *reinterpret_cast<const unsigned*>(base + r0 * A_STRIDE + 16);
        unsigned a3 = *reinterpret_cast<const unsigned*>(base + (r0 + 8) * A_STRIDE + 16);
        const uint2* wrow = wfrag + s * 512 + lane;
        #pragma unroll
        for (int t = 0; t < 16; t++) {
            uint2 b = __ldg(wrow + t * 32);
            mma_bf16(acc[t][0], acc[t][1], acc[t][2], acc[t][3],
                     a0, a1, a2, a3, b.x, b.y);
        }
    }
}

__global__ void __launch_bounds__(256, 2) fused_mlp_mma(
    const float* __restrict__ b1, const float* __restrict__ b2,
    float* __restrict__ out, int n_nodes)
{
    extern __shared__ __align__(16) unsigned char smem[];
    const int tid  = threadIdx.x;
    const int wid  = tid >> 5;
    const int lane = tid & 31;
    const int node0 = blockIdx.x * TILE_M;
    const int r0 = wid * 16 + (lane >> 2);     // this thread's base row in tile
    const int cb = (lane & 3) * 2;             // base col within n-tile

    // biases -> smem
    if (tid < 128) {
        ((float*)(smem + B1_OFF))[tid] = __ldg(b1 + tid);
        ((float*)(smem + B2_OFF))[tid] = __ldg(b2 + tid);
    }

    // ---- load X tile, split into Ahi/Alo smem images ----
    #pragma unroll 4
    for (int i = 0; i < 16; i++) {
        int idx = tid + i * 256;               // 128 rows x 32 float4
        int row = idx >> 5, c4 = idx & 31;
        int gn = node0 + row;
        float4 v = make_float4(0.f, 0.f, 0.f, 0.f);
        if (gn < n_nodes)
            v = __ldg(reinterpret_cast<const float4*>(g_comb) + (size_t)gn * 32 + c4);
        unsigned h01, l01, h23, l23;
        split2(v.x, v.y, h01, l01);
        split2(v.z, v.w, h23, l23);
        unsigned off = row * A_STRIDE + c4 * 8;
        *reinterpret_cast<uint2*>(smem + AH_OFF + off) = make_uint2(h01, h23);
        *reinterpret_cast<uint2*>(smem + AL_OFF + off) = make_uint2(l01, l23);
    }
    __syncthreads();

    float acc[16][4];

    // ===== GEMM1: 3-pass split, W1 =====
    #pragma unroll
    for (int t = 0; t < 16; t++)
        acc[t][0] = acc[t][1] = acc[t][2] = acc[t][3] = 0.f;

    gemm_pass(smem, AH_OFF, g_wfrag,        acc, r0, lane);   // Ahi*W1hi
    gemm_pass(smem, AH_OFF, g_wfrag + 4096, acc, r0, lane);   // Ahi*W1lo
    gemm_pass(smem, AL_OFF, g_wfrag,        acc, r0, lane);   // Alo*W1hi
    __syncthreads();

    // ---- epilogue1: +b1, relu, re-split into A images ----
    #pragma unroll
    for (int t = 0; t < 16; t++) {
        int c = t * 8 + cb;
        float bb0 = ((float*)(smem + B1_OFF))[c];
        float bb1 = ((float*)(smem + B1_OFF))[c + 1];
        float h0 = fmaxf(acc[t][0] + bb0, 0.f);
        float h1 = fmaxf(acc[t][1] + bb1, 0.f);
        float h2 = fmaxf(acc[t][2] + bb0, 0.f);
        float h3 = fmaxf(acc[t][3] + bb1, 0.f);
        unsigned hp, lp;
        unsigned off0 = r0 * A_STRIDE + c * 2;
        unsigned off1 = (r0 + 8) * A_STRIDE + c * 2;
        split2(h0, h1, hp, lp);
        *reinterpret_cast<unsigned*>(smem + AH_OFF + off0) = hp;
        *reinterpret_cast<unsigned*>(smem + AL_OFF + off0) = lp;
        split2(h2, h3, hp, lp);
        *reinterpret_cast<unsigned*>(smem + AH_OFF + off1) = hp;
        *reinterpret_cast<unsigned*>(smem + AL_OFF + off1) = lp;
    }
    __syncthreads();

    // ===== GEMM2: 3-pass split, W2 =====
    #pragma unroll
    for (int t = 0; t < 16; t++)
        acc[t][0] = acc[t][1] = acc[t][2] = acc[t][3] = 0.f;

    gemm_pass(smem, AH_OFF, g_wfrag + 8192,  acc, r0, lane);  // Hhi*W2hi
    gemm_pass(smem, AH_OFF, g_wfrag + 12288, acc, r0, lane);  // Hhi*W2lo
    gemm_pass(smem, AL_OFF, g_wfrag + 8192,  acc, r0, lane);  // Hlo*W2hi

    // ---- epilogue2: +b2 -> out ----
    const int gnA = node0 + r0;
    const int gnB = gnA + 8;
    #pragma unroll
    for (int t = 0; t < 16; t++) {
        int c = t * 8 + cb;
        float bb0 = ((float*)(smem + B2_OFF))[c];
        float bb1 = ((float*)(smem + B2_OFF))[c + 1];
        if (gnA < n_nodes) {
            float2 o = make_float2(acc[t][0] + bb0, acc[t][1] + bb1);
            *reinterpret_cast<float2*>(out + (size_t)gnA * D + c) = o;
        }
        if (gnB < n_nodes) {
            float2 o = make_float2(acc[t][2] + bb0, acc[t][3] + bb1);
            *reinterpret_cast<float2*>(out + (size_t)gnB * D + c) = o;
        }
    }
}

// ---------------------------------------------------------------------------
// Launch
// ---------------------------------------------------------------------------
extern "C" void kernel_launch(void* const* d_in, const int* in_sizes, int n_in,
                              void* d_out, int out_size)
{
    const int*   indices  = (const int*)d_in[0];
    const float* values   = (const float*)d_in[1];
    const float* features = (const float*)d_in[2];
    const float* W1       = (const float*)d_in[3];
    const float* b1       = (const float*)d_in[4];
    const float* W2       = (const float*)d_in[5];
    const float* b2       = (const float*)d_in[6];
    float*       out      = (float*)d_out;

    const int n_edges = in_sizes[1];
    const int n_nodes = in_sizes[2] / D;
    const int* row_idx = indices;
    const int* col_idx = indices + n_edges;

    static int smem_set = 0;
    if (!smem_set) {
        cudaFuncSetAttribute(fused_mlp_mma,
                             cudaFuncAttributeMaxDynamicSharedMemorySize,
                             SMEM_TOT);
        smem_set = 1;
    }

    // 1) combined = features
    init_combined<<<(n_nodes * (D / 4) + 255) / 256, 256>>>(features,
                                                            n_nodes * (D / 4));
    // 2) combined[row] += v * features[col]
    edge_scatter<<<(n_edges + 7) / 8, 256>>>(row_idx, col_idx, values,
                                             features, n_edges);
    // 3) weight split -> fragment images
    wprep<<<32, 256>>>(W1, W2);

    // 4) tensor-core MLP (mma.sync bf16, 3-pass split)
    fused_mlp_mma<<<(n_nodes + TILE_M - 1) / TILE_M, 256, SMEM_TOT>>>(
        b1, b2, out, n_nodes);
}